// round 1
// baseline (speedup 1.0000x reference)
#include <cuda_runtime.h>
#include <math.h>

// Problem constants (shapes fixed by the dataset; runtime sizes derived from in_sizes)
#define DIM      64
#define NREL     16
#define NCOLS    (NREL * DIM)        // 1024
#define MAX_N    120000
#define MAX_E    1600000

// ---- scratch (device globals; no allocations allowed) ----
__device__ __align__(256) float    g_trans[(size_t)MAX_N * NCOLS];  // [n][rel*64+k]
__device__ __align__(256) float    g_att[MAX_E];
__device__ __align__(256) float    g_ex[MAX_E];
__device__ __align__(256) unsigned g_nmax[MAX_N];   // order-encoded float max
__device__ __align__(256) float    g_denom[MAX_N];

// order-preserving float<->uint encoding (total order, works for negatives)
__device__ __forceinline__ unsigned enc_f(float f) {
    unsigned b = __float_as_uint(f);
    return (b & 0x80000000u) ? ~b : (b | 0x80000000u);
}
__device__ __forceinline__ float dec_f(unsigned u) {
    return __uint_as_float((u & 0x80000000u) ? (u & 0x7FFFFFFFu) : ~u);
}

// ---- K0: init per-node accumulators ----
__global__ void init_kernel(int n) {
    int i = blockIdx.x * blockDim.x + threadIdx.x;
    if (i < n) { g_nmax[i] = 0u; g_denom[i] = 0.0f; }  // enc 0 < enc(any finite float)
}

// ---- K1: trans[m][r*64+k] = sum_d emb[m][d] * W[r][d][k] ----
// CTA tile: 128 rows x 64 cols (one relation per blockIdx.y). 256 threads,
// 8x4 register microtile per thread. K=64 fully staged in smem.
__global__ __launch_bounds__(256) void gemm_kernel(
    const float* __restrict__ emb, const float* __restrict__ W, int M)
{
    __shared__ __align__(16) float As[128 * 64];  // 32 KB, row-major [m][d]
    __shared__ __align__(16) float Bs[64 * 64];   // 16 KB, [d][k]

    const int tid  = threadIdx.x;
    const int m0   = blockIdx.x * 128;
    const int rrel = blockIdx.y;
    const float* Wr = W + (size_t)rrel * (DIM * DIM);

    // load A tile (128x64 fp32) with float4, zero-fill past M
    {
        int c4 = tid & 15;   // float4 column
        int r  = tid >> 4;   // 0..15
        #pragma unroll
        for (int p = 0; p < 8; p++) {
            int row = r + p * 16;
            int gm  = m0 + row;
            float4 v = (gm < M)
                ? ((const float4*)(emb + (size_t)gm * DIM))[c4]
                : make_float4(0.f, 0.f, 0.f, 0.f);
            *(float4*)&As[row * DIM + c4 * 4] = v;
        }
    }
    // load B tile (64x64) — same memory layout as W[r]
    #pragma unroll
    for (int p = 0; p < 4; p++) {
        ((float4*)Bs)[tid + p * 256] = ((const float4*)Wr)[tid + p * 256];
    }
    __syncthreads();

    const int trow = (tid >> 4) * 8;  // 0..120
    const int tcol = (tid & 15) * 4;  // 0..60
    float acc[8][4] = {};

    #pragma unroll 8
    for (int d = 0; d < DIM; d++) {
        float4 b = *(const float4*)&Bs[d * DIM + tcol];
        float a[8];
        #pragma unroll
        for (int i = 0; i < 8; i++) a[i] = As[(trow + i) * DIM + d];
        #pragma unroll
        for (int i = 0; i < 8; i++) {
            acc[i][0] = fmaf(a[i], b.x, acc[i][0]);
            acc[i][1] = fmaf(a[i], b.y, acc[i][1]);
            acc[i][2] = fmaf(a[i], b.z, acc[i][2]);
            acc[i][3] = fmaf(a[i], b.w, acc[i][3]);
        }
    }

    #pragma unroll
    for (int i = 0; i < 8; i++) {
        int gm = m0 + trow + i;
        if (gm < M) {
            *(float4*)&g_trans[(size_t)gm * NCOLS + rrel * DIM + tcol] =
                make_float4(acc[i][0], acc[i][1], acc[i][2], acc[i][3]);
        }
    }
}

// ---- K2: per-edge attention logit + segment max ----
// One warp per edge: each lane handles 2 of the 64 channels.
__global__ __launch_bounds__(256) void att_kernel(
    const int* __restrict__ src, const int* __restrict__ dst,
    const int* __restrict__ typ, const float* __restrict__ rel, int E)
{
    int gw   = (blockIdx.x * blockDim.x + threadIdx.x) >> 5;
    int lane = threadIdx.x & 31;
    if (gw >= E) return;

    int s = src[gw], d = dst[gw], r = typ[gw];
    const float2* t  = (const float2*)(g_trans + (size_t)s * NCOLS + r * DIM);
    const float2* h  = (const float2*)(g_trans + (size_t)d * NCOLS + r * DIM);
    const float2* re = (const float2*)(rel + (size_t)r * DIM);

    float2 tv = t[lane], hv = h[lane], rv = re[lane];
    float p = tv.x * tanhf(hv.x + rv.x) + tv.y * tanhf(hv.y + rv.y);

    #pragma unroll
    for (int o = 16; o > 0; o >>= 1) p += __shfl_xor_sync(0xffffffffu, p, o);

    if (lane == 0) {
        g_att[gw] = p;
        atomicMax(&g_nmax[d], enc_f(p));
    }
}

// ---- K3: ex = exp(att - max[dst]); segment sum ----
__global__ void exp_kernel(const int* __restrict__ dst, int E) {
    int i = blockIdx.x * blockDim.x + threadIdx.x;
    if (i < E) {
        int d  = dst[i];
        float m = dec_f(g_nmax[d]);
        float e = expf(g_att[i] - m);
        g_ex[i] = e;
        atomicAdd(&g_denom[d], e);
    }
}

// ---- K4: normalize ----
__global__ void norm_kernel(const int* __restrict__ dst, float* __restrict__ out, int E) {
    int i = blockIdx.x * blockDim.x + threadIdx.x;
    if (i < E) out[i] = g_ex[i] / g_denom[dst[i]];
}

extern "C" void kernel_launch(void* const* d_in, const int* in_sizes, int n_in,
                              void* d_out, int out_size)
{
    const float* emb = (const float*)d_in[0];  // [N, 64]
    const float* rel = (const float*)d_in[1];  // [16, 64]
    const float* W   = (const float*)d_in[2];  // [16, 64, 64]
    const int*   src = (const int*)d_in[3];    // [E]
    const int*   dst = (const int*)d_in[4];    // [E]
    const int*   typ = (const int*)d_in[5];    // [E]
    float*       out = (float*)d_out;          // [E, 1]

    int M = in_sizes[0] / DIM;
    int E = in_sizes[3];

    init_kernel<<<(M + 255) / 256, 256>>>(M);
    gemm_kernel<<<dim3((M + 127) / 128, NREL), 256>>>(emb, W, M);
    att_kernel<<<(E + 7) / 8, 256>>>(src, dst, typ, rel, E);
    exp_kernel<<<(E + 255) / 256, 256>>>(dst, E);
    norm_kernel<<<(E + 255) / 256, 256>>>(dst, out, E);
}